// round 12
// baseline (speedup 1.0000x reference)
#include <cuda_runtime.h>
#include <cstdint>

// Shapes (fixed by the problem)
#define BB   32
#define SS   128
#define VV   8192
#define EE   256
#define MR   (BB*SS)

// G1 split-K config
#define KSPLIT 4
#define KCHUNK (VV/KSPLIT)   // 2048
#define BK32   32
#define STR    36            // smem row stride in uint32 (32 + 4 pad)
#define TILE_U32 (128 * STR)                 // one stage of one operand
#define G1_DSMEM (4 * TILE_U32 * 4)          // 73728 bytes

// ---------------- scratch (device globals; no allocation) ----------------
__device__ float g_p1[KSPLIT][MR][EE];  // G1 split-K partials 16 MB
__device__ float g_h[MR*EE];            // h     [4096,256]
__device__ float g_s[MR];               // rowsum(h)
__device__ float g_weff[BB*EE*EE];      // Weff  [32,256,256]
__device__ float g_y[MR*EE];            // y     [4096,256]
__device__ float g_part[64*BB*EE];      // G4 split-K partials
__device__ float g_y2[BB*EE];           // y2    [32,256]

// ---------------- helpers ----------------
__device__ __forceinline__ uint32_t f2tf32(float f) {
    uint32_t u;
    asm("cvt.rna.tf32.f32 %0, %1;" : "=r"(u) : "f"(f));
    return u;
}

__device__ __forceinline__ uint32_t smem_u32(const void* p) {
    uint32_t a;
    asm("{ .reg .u64 t; cvta.to.shared.u64 t, %1; cvt.u32.u64 %0, t; }" : "=r"(a) : "l"(p));
    return a;
}

__device__ __forceinline__ uint4 ldsm_x4(uint32_t addr) {
    uint4 r;
    asm volatile("ldmatrix.sync.aligned.m8n8.x4.shared.b16 {%0,%1,%2,%3}, [%4];"
        : "=r"(r.x), "=r"(r.y), "=r"(r.z), "=r"(r.w) : "r"(addr));
    return r;
}

__device__ __forceinline__ void mma_tf32(float c[4], const uint4 a, const uint32_t b0, const uint32_t b1) {
    asm volatile(
        "mma.sync.aligned.m16n8k8.row.col.f32.tf32.tf32.f32 "
        "{%0,%1,%2,%3}, {%4,%5,%6,%7}, {%8,%9}, {%0,%1,%2,%3};"
        : "+f"(c[0]), "+f"(c[1]), "+f"(c[2]), "+f"(c[3])
        : "r"(a.x), "r"(a.y), "r"(a.z), "r"(a.w), "r"(b0), "r"(b1));
}

// profile-slot shifter: 1 dummy -> ncu's fixed slot (our 4th launch) = weff
__global__ void dummy_kernel() {}

// ===================================================================
// G1 split-K: partial[kz] = x[:, kz*2048:+2048] @ w_emb^T chunk
// CTA tile 128m x 128n x 32k, 128 threads = 4 warps (2m x 2n),
// warp tile 64x64, BK=32 full-line staging. Staging STS interleaved
// between ks group 2 and 3 to shrink the barrier-phase bubble.
// grid (2=n, 32=m, 4=kz) = 256 CTAs, 2 CTAs/SM.
// ===================================================================
__global__ void __launch_bounds__(128, 2) g1_kernel(
    const float* __restrict__ x, const float* __restrict__ w_emb)
{
    extern __shared__ uint32_t dsm[];
    uint32_t* sA[2] = { dsm,               dsm + TILE_U32 };
    uint32_t* sB[2] = { dsm + 2*TILE_U32,  dsm + 3*TILE_U32 };

    const int tid  = threadIdx.x;
    const int lane = tid & 31;
    const int warp = tid >> 5;
    const int wm = (warp >> 1) * 64;
    const int wn = (warp & 1) * 64;
    const long bm = (long)blockIdx.y * 128;
    const long bn = (long)blockIdx.x * 128;
    const long kbase = (long)blockIdx.z * KCHUNK;

    const int srow8 = tid >> 3;             // 0..15
    const int sc8   = (tid & 7) * 4;        // 0,4,...,28
    const float* Abase = x + (bm + srow8) * VV + kbase + sc8;
    const float* Bbase = w_emb + (bn + srow8) * VV + kbase + sc8;
    const long rowstep = 16L * VV;

    const uint32_t sAb[2] = { smem_u32(sA[0]), smem_u32(sA[1]) };
    const uint32_t sBb[2] = { smem_u32(sB[0]), smem_u32(sB[1]) };

    const int aRow = ((lane >> 3) & 1) * 8 + (lane & 7);
    const int aCol = (lane >> 4) * 4;
    const int bRow = ((lane >> 4) & 1) * 8 + (lane & 7);
    const int bCol = ((lane >> 3) & 1) * 4;

    float acc[4][8][4] = {};
    float4 pa[8], pb[8];

    #pragma unroll
    for (int i = 0; i < 8; i++) {
        pa[i] = *reinterpret_cast<const float4*>(Abase + i * rowstep);
        pb[i] = *reinterpret_cast<const float4*>(Bbase + i * rowstep);
    }
    #pragma unroll
    for (int i = 0; i < 8; i++) {
        uint4 au = { f2tf32(pa[i].x), f2tf32(pa[i].y), f2tf32(pa[i].z), f2tf32(pa[i].w) };
        uint4 bu = { f2tf32(pb[i].x), f2tf32(pb[i].y), f2tf32(pb[i].z), f2tf32(pb[i].w) };
        *reinterpret_cast<uint4*>(&sA[0][(srow8 + 16 * i) * STR + sc8]) = au;
        *reinterpret_cast<uint4*>(&sB[0][(srow8 + 16 * i) * STR + sc8]) = bu;
    }
    __syncthreads();

    const int nkt = KCHUNK / BK32;          // 64
    for (int kt = 0; kt < nkt; kt++) {
        const int cur = kt & 1;
        const bool more = (kt + 1) < nkt;

        if (more) {
            const float* Ap = Abase + (kt + 1) * BK32;
            const float* Bp = Bbase + (kt + 1) * BK32;
            #pragma unroll
            for (int i = 0; i < 8; i++) {
                pa[i] = *reinterpret_cast<const float4*>(Ap + i * rowstep);
                pb[i] = *reinterpret_cast<const float4*>(Bp + i * rowstep);
            }
        }

        const uint32_t ab = sAb[cur];
        const uint32_t bb = sBb[cur];

        // ks groups 0..2
        #pragma unroll
        for (int ks = 0; ks < 3; ks++) {
            const int k0 = ks * 8;
            uint4 af[4], bf[4];
            #pragma unroll
            for (int mi = 0; mi < 4; mi++)
                af[mi] = ldsm_x4(ab + ((wm + mi * 16 + aRow) * STR + k0 + aCol) * 4);
            #pragma unroll
            for (int q = 0; q < 4; q++)
                bf[q] = ldsm_x4(bb + ((wn + q * 16 + bRow) * STR + k0 + bCol) * 4);
            #pragma unroll
            for (int mi = 0; mi < 4; mi++) {
                #pragma unroll
                for (int nt = 0; nt < 8; nt++) {
                    const int q = nt >> 1;
                    if (nt & 1) mma_tf32(acc[mi][nt], af[mi], bf[q].z, bf[q].w);
                    else        mma_tf32(acc[mi][nt], af[mi], bf[q].x, bf[q].y);
                }
            }
        }

        // staging store mid-tile (buffer cur^1; readers still on cur)
        if (more) {
            uint32_t* dA = sA[cur ^ 1];
            uint32_t* dB = sB[cur ^ 1];
            #pragma unroll
            for (int i = 0; i < 8; i++) {
                uint4 au = { f2tf32(pa[i].x), f2tf32(pa[i].y), f2tf32(pa[i].z), f2tf32(pa[i].w) };
                uint4 bu = { f2tf32(pb[i].x), f2tf32(pb[i].y), f2tf32(pb[i].z), f2tf32(pb[i].w) };
                *reinterpret_cast<uint4*>(&dA[(srow8 + 16 * i) * STR + sc8]) = au;
                *reinterpret_cast<uint4*>(&dB[(srow8 + 16 * i) * STR + sc8]) = bu;
            }
        }

        // final ks group 3
        {
            const int k0 = 24;
            uint4 af[4], bf[4];
            #pragma unroll
            for (int mi = 0; mi < 4; mi++)
                af[mi] = ldsm_x4(ab + ((wm + mi * 16 + aRow) * STR + k0 + aCol) * 4);
            #pragma unroll
            for (int q = 0; q < 4; q++)
                bf[q] = ldsm_x4(bb + ((wn + q * 16 + bRow) * STR + k0 + bCol) * 4);
            #pragma unroll
            for (int mi = 0; mi < 4; mi++) {
                #pragma unroll
                for (int nt = 0; nt < 8; nt++) {
                    const int q = nt >> 1;
                    if (nt & 1) mma_tf32(acc[mi][nt], af[mi], bf[q].z, bf[q].w);
                    else        mma_tf32(acc[mi][nt], af[mi], bf[q].x, bf[q].y);
                }
            }
        }
        __syncthreads();
    }

    float* P = &g_p1[blockIdx.z][0][0];
    #pragma unroll
    for (int mi = 0; mi < 4; mi++) {
        #pragma unroll
        for (int nt = 0; nt < 8; nt++) {
            long row = bm + wm + mi * 16 + (lane >> 2);
            long col = bn + wn + nt * 8 + (lane & 3) * 2;
            *reinterpret_cast<float2*>(&P[row * EE + col]) =
                make_float2(acc[mi][nt][0], acc[mi][nt][1]);
            *reinterpret_cast<float2*>(&P[(row + 8) * EE + col]) =
                make_float2(acc[mi][nt][2], acc[mi][nt][3]);
        }
    }
}

// ===================================================================
// G3 tensorized: y[b] = relu(h[b] @ Weff[b]^T + b_red)
// Same body as g1: CTA 128m x 128n x 32k, warp 64x64, K=256 (8 tiles).
// grid (2 = n-tile, 32 = batch) x 128, dynamic smem 72 KB.
// ===================================================================
__global__ void __launch_bounds__(128, 2) g3_kernel(const float* __restrict__ b_red)
{
    extern __shared__ uint32_t dsm[];
    uint32_t* sA[2] = { dsm,               dsm + TILE_U32 };
    uint32_t* sB[2] = { dsm + 2*TILE_U32,  dsm + 3*TILE_U32 };

    const int tid  = threadIdx.x;
    const int lane = tid & 31;
    const int warp = tid >> 5;
    const int wm = (warp >> 1) * 64;
    const int wn = (warp & 1) * 64;
    const int batch = blockIdx.y;
    const long bn = (long)blockIdx.x * 128;

    const float* A = g_h + (long)batch * SS * EE;
    const float* B = g_weff + (long)batch * EE * EE;
    float* C = g_y + (long)batch * SS * EE;

    const int srow8 = tid >> 3;
    const int sc8   = (tid & 7) * 4;
    const float* Abase = A + (long)srow8 * EE + sc8;
    const float* Bbase = B + (bn + srow8) * EE + sc8;
    const long rowstep = 16L * EE;

    const uint32_t sAb[2] = { smem_u32(sA[0]), smem_u32(sA[1]) };
    const uint32_t sBb[2] = { smem_u32(sB[0]), smem_u32(sB[1]) };

    const int aRow = ((lane >> 3) & 1) * 8 + (lane & 7);
    const int aCol = (lane >> 4) * 4;
    const int bRow = ((lane >> 4) & 1) * 8 + (lane & 7);
    const int bCol = ((lane >> 3) & 1) * 4;

    float acc[4][8][4] = {};
    float4 pa[8], pb[8];

    #pragma unroll
    for (int i = 0; i < 8; i++) {
        pa[i] = *reinterpret_cast<const float4*>(Abase + i * rowstep);
        pb[i] = *reinterpret_cast<const float4*>(Bbase + i * rowstep);
    }
    #pragma unroll
    for (int i = 0; i < 8; i++) {
        uint4 au = { f2tf32(pa[i].x), f2tf32(pa[i].y), f2tf32(pa[i].z), f2tf32(pa[i].w) };
        uint4 bu = { f2tf32(pb[i].x), f2tf32(pb[i].y), f2tf32(pb[i].z), f2tf32(pb[i].w) };
        *reinterpret_cast<uint4*>(&sA[0][(srow8 + 16 * i) * STR + sc8]) = au;
        *reinterpret_cast<uint4*>(&sB[0][(srow8 + 16 * i) * STR + sc8]) = bu;
    }
    __syncthreads();

    const int nkt = EE / BK32;              // 8
    for (int kt = 0; kt < nkt; kt++) {
        const int cur = kt & 1;
        const bool more = (kt + 1) < nkt;

        if (more) {
            const float* Ap = Abase + (kt + 1) * BK32;
            const float* Bp = Bbase + (kt + 1) * BK32;
            #pragma unroll
            for (int i = 0; i < 8; i++) {
                pa[i] = *reinterpret_cast<const float4*>(Ap + i * rowstep);
                pb[i] = *reinterpret_cast<const float4*>(Bp + i * rowstep);
            }
        }

        const uint32_t ab = sAb[cur];
        const uint32_t bb = sBb[cur];
        #pragma unroll
        for (int ks = 0; ks < 4; ks++) {
            const int k0 = ks * 8;
            uint4 af[4], bf[4];
            #pragma unroll
            for (int mi = 0; mi < 4; mi++)
                af[mi] = ldsm_x4(ab + ((wm + mi * 16 + aRow) * STR + k0 + aCol) * 4);
            #pragma unroll
            for (int q = 0; q < 4; q++)
                bf[q] = ldsm_x4(bb + ((wn + q * 16 + bRow) * STR + k0 + bCol) * 4);
            #pragma unroll
            for (int mi = 0; mi < 4; mi++) {
                #pragma unroll
                for (int nt = 0; nt < 8; nt++) {
                    const int q = nt >> 1;
                    if (nt & 1) mma_tf32(acc[mi][nt], af[mi], bf[q].z, bf[q].w);
                    else        mma_tf32(acc[mi][nt], af[mi], bf[q].x, bf[q].y);
                }
            }
        }

        if (more) {
            uint32_t* dA = sA[cur ^ 1];
            uint32_t* dB = sB[cur ^ 1];
            #pragma unroll
            for (int i = 0; i < 8; i++) {
                uint4 au = { f2tf32(pa[i].x), f2tf32(pa[i].y), f2tf32(pa[i].z), f2tf32(pa[i].w) };
                uint4 bu = { f2tf32(pb[i].x), f2tf32(pb[i].y), f2tf32(pb[i].z), f2tf32(pb[i].w) };
                *reinterpret_cast<uint4*>(&dA[(srow8 + 16 * i) * STR + sc8]) = au;
                *reinterpret_cast<uint4*>(&dB[(srow8 + 16 * i) * STR + sc8]) = bu;
            }
        }
        __syncthreads();
    }

    // epilogue: bias + relu
    #pragma unroll
    for (int mi = 0; mi < 4; mi++) {
        #pragma unroll
        for (int nt = 0; nt < 8; nt++) {
            long row = wm + mi * 16 + (lane >> 2);
            long col = bn + wn + nt * 8 + (lane & 3) * 2;
            float b0 = b_red[col], b1 = b_red[col + 1];
            float v0 = fmaxf(acc[mi][nt][0] + b0, 0.f);
            float v1 = fmaxf(acc[mi][nt][1] + b1, 0.f);
            float v2 = fmaxf(acc[mi][nt][2] + b0, 0.f);
            float v3 = fmaxf(acc[mi][nt][3] + b1, 0.f);
            *reinterpret_cast<float2*>(&C[row * EE + col])       = make_float2(v0, v1);
            *reinterpret_cast<float2*>(&C[(row + 8) * EE + col]) = make_float2(v2, v3);
        }
    }
}

// ---------------- h = relu(sum partials + bias); rowsum -> s ----------------
__global__ void __launch_bounds__(256) h_reduce_kernel(const float* __restrict__ b_emb)
{
    const int row = blockIdx.x;
    const int e = threadIdx.x;
    const int lane = e & 31;
    const int warp = e >> 5;

    float v = b_emb[e];
    #pragma unroll
    for (int ks = 0; ks < KSPLIT; ks++) v += g_p1[ks][row][e];
    v = fmaxf(v, 0.f);
    g_h[(long)row * EE + e] = v;

    float s = v;
    #pragma unroll
    for (int o = 16; o; o >>= 1) s += __shfl_xor_sync(0xffffffffu, s, o);
    __shared__ float red[8];
    if (lane == 0) red[warp] = s;
    __syncthreads();
    if (e == 0) {
        float t = 0.f;
        #pragma unroll
        for (int i = 0; i < 8; i++) t += red[i];
        g_s[row] = t;
    }
}

// ---------------- G2: Weff[b,e,j] = sum_k s[b,k]*w_red[e, k*E+j] ----------------
__global__ void __launch_bounds__(256) weff_kernel(const float* __restrict__ w_red)
{
    __shared__ float ss[BB * SS];
    int tid = threadIdx.x;
    for (int i = tid; i < BB * SS; i += 256) ss[i] = g_s[i];
    __syncthreads();

    int e = blockIdx.x;
    const float* w = w_red + (long)e * (SS * EE) + tid;
    float acc[BB];
    #pragma unroll
    for (int b = 0; b < BB; b++) acc[b] = 0.f;

    #pragma unroll 8
    for (int k = 0; k < SS; k++) {
        float wv = w[(long)k * EE];
        #pragma unroll
        for (int b = 0; b < BB; b++) acc[b] += ss[b * SS + k] * wv;
    }
    #pragma unroll
    for (int b = 0; b < BB; b++)
        g_weff[(long)b * (EE * EE) + (long)e * EE + tid] = acc[b];
}

// ---------------- G4 split-K ----------------
__global__ void __launch_bounds__(256) red2_partial_kernel(const float* __restrict__ w_red2)
{
    __shared__ float ys[32][68];
    __shared__ float ws[64][65];
    int tid = threadIdx.x;
    int e_base = blockIdx.x * 64;
    long k_base = (long)blockIdx.y * 512;
    int el = tid & 63;
    int bb = (tid >> 6) * 8;
    float acc[8] = {};

    for (int k0 = 0; k0 < 512; k0 += 64) {
        #pragma unroll
        for (int i = 0; i < 2; i++) {
            int idx = tid + i * 256;
            int row = idx >> 4;
            int c4 = (idx & 15) * 4;
            float4 v = *reinterpret_cast<const float4*>(
                &g_y[(long)row * (SS * EE) + k_base + k0 + c4]);
            *reinterpret_cast<float4*>(&ys[row][c4]) = v;
        }
        #pragma unroll
        for (int i = 0; i < 4; i++) {
            int idx = tid + i * 256;
            int row = idx >> 4;
            int c4 = (idx & 15) * 4;
            float4 v = *reinterpret_cast<const float4*>(
                &w_red2[(long)(e_base + row) * (SS * EE) + k_base + k0 + c4]);
            ws[row][c4] = v.x; ws[row][c4 + 1] = v.y;
            ws[row][c4 + 2] = v.z; ws[row][c4 + 3] = v.w;
        }
        __syncthreads();
        #pragma unroll 8
        for (int kk = 0; kk < 64; kk++) {
            float wv = ws[el][kk];
            #pragma unroll
            for (int i = 0; i < 8; i++) acc[i] += ys[bb + i][kk] * wv;
        }
        __syncthreads();
    }
    #pragma unroll
    for (int i = 0; i < 8; i++)
        g_part[(long)blockIdx.y * (BB * EE) + (bb + i) * EE + e_base + el] = acc[i];
}

__global__ void red2_reduce_kernel(const float* __restrict__ b_red2)
{
    int idx = blockIdx.x * 256 + threadIdx.x;
    float s = b_red2[idx & 255];
    #pragma unroll 8
    for (int ks = 0; ks < 64; ks++) s += g_part[(long)ks * (BB * EE) + idx];
    g_y2[idx] = fmaxf(s, 0.f);
}

// ---------------- G5: out = y2 @ w_out^T + b_out ----------------
__global__ void __launch_bounds__(256) out_kernel(
    const float* __restrict__ w_out, const float* __restrict__ b_out,
    float* __restrict__ out)
{
    __shared__ float ys[32][68];
    __shared__ float ws[64][65];
    int tid = threadIdx.x;
    int v_base = blockIdx.x * 64;
    int vl = tid & 63;
    int bb = (tid >> 6) * 8;
    float acc[8] = {};

    for (int k0 = 0; k0 < EE; k0 += 64) {
        #pragma unroll
        for (int i = 0; i < 2; i++) {
            int idx = tid + i * 256;
            int row = idx >> 4;
            int c4 = (idx & 15) * 4;
            float4 v = *reinterpret_cast<const float4*>(&g_y2[row * EE + k0 + c4]);
            *reinterpret_cast<float4*>(&ys[row][c4]) = v;
        }
        #pragma unroll
        for (int i = 0; i < 4; i++) {
            int idx = tid + i * 256;
            int row = idx >> 4;
            int c4 = (idx & 15) * 4;
            float4 v = *reinterpret_cast<const float4*>(
                &w_out[(long)(v_base + row) * EE + k0 + c4]);
            ws[row][c4] = v.x; ws[row][c4 + 1] = v.y;
            ws[row][c4 + 2] = v.z; ws[row][c4 + 3] = v.w;
        }
        __syncthreads();
        #pragma unroll 8
        for (int kk = 0; kk < 64; kk++) {
            float wv = ws[vl][kk];
            #pragma unroll
            for (int i = 0; i < 8; i++) acc[i] += ys[bb + i][kk] * wv;
        }
        __syncthreads();
    }
    float bo = b_out[v_base + vl];
    #pragma unroll
    for (int i = 0; i < 8; i++)
        out[(long)(bb + i) * VV + v_base + vl] = acc[i] + bo;
}

// ---------------- launch ----------------
extern "C" void kernel_launch(void* const* d_in, const int* in_sizes, int n_in,
                              void* d_out, int out_size)
{
    const float* x      = (const float*)d_in[0];
    const float* w_emb  = (const float*)d_in[1];
    const float* b_emb  = (const float*)d_in[2];
    const float* w_red  = (const float*)d_in[3];
    const float* b_red  = (const float*)d_in[4];
    const float* w_red2 = (const float*)d_in[5];
    const float* b_red2 = (const float*)d_in[6];
    const float* w_out  = (const float*)d_in[7];
    const float* b_out  = (const float*)d_in[8];
    float* out = (float*)d_out;

    cudaFuncSetAttribute(g1_kernel, cudaFuncAttributeMaxDynamicSharedMemorySize, G1_DSMEM);
    cudaFuncSetAttribute(g3_kernel, cudaFuncAttributeMaxDynamicSharedMemorySize, G1_DSMEM);

    dummy_kernel<<<1, 32>>>();                                   // 1 dummy: ncu slot -> weff
    g1_kernel<<<dim3(2, 32, KSPLIT), 128, G1_DSMEM>>>(x, w_emb); // G1 partials
    h_reduce_kernel<<<MR, 256>>>(b_emb);                         // h + rowsum
    weff_kernel<<<256, 256>>>(w_red);                            // Weff  (profiled)
    g3_kernel<<<dim3(2, 32), 128, G1_DSMEM>>>(b_red);            // y (tensorized)
    red2_partial_kernel<<<dim3(4, 64), 256>>>(w_red2);           // G4 partials
    red2_reduce_kernel<<<32, 256>>>(b_red2);                     // y2
    out_kernel<<<128, 256>>>(w_out, b_out, out);                 // out
}

// round 13
// speedup vs baseline: 1.1139x; 1.1139x over previous
#include <cuda_runtime.h>
#include <cstdint>

// Shapes (fixed by the problem)
#define BB   32
#define SS   128
#define VV   8192
#define EE   256
#define MR   (BB*SS)

// G1 split-K config
#define KSPLIT 4
#define KCHUNK (VV/KSPLIT)   // 2048
#define BK32   32
#define STR    36            // smem row stride in uint32 (32 + 4 pad)
#define TILE_U32 (128 * STR)                 // one stage of one operand
#define G1_DSMEM (4 * TILE_U32 * 4)          // 73728 bytes

// ---------------- scratch (device globals; no allocation) ----------------
__device__ float g_p1[KSPLIT][MR][EE];  // G1 split-K partials 16 MB
__device__ float g_h[MR*EE];            // h     [4096,256]
__device__ float g_s[MR];               // rowsum(h)
__device__ float g_weff[BB*EE*EE];      // Weff  [32,256,256]
__device__ float g_y[MR*EE];            // y     [4096,256]
__device__ float g_part[64*BB*EE];      // G4 split-K partials
__device__ float g_y2[BB*EE];           // y2    [32,256]

// ---------------- helpers ----------------
__device__ __forceinline__ uint32_t f2tf32(float f) {
    uint32_t u;
    asm("cvt.rna.tf32.f32 %0, %1;" : "=r"(u) : "f"(f));
    return u;
}

__device__ __forceinline__ uint32_t smem_u32(const void* p) {
    uint32_t a;
    asm("{ .reg .u64 t; cvta.to.shared.u64 t, %1; cvt.u32.u64 %0, t; }" : "=r"(a) : "l"(p));
    return a;
}

__device__ __forceinline__ uint4 ldsm_x4(uint32_t addr) {
    uint4 r;
    asm volatile("ldmatrix.sync.aligned.m8n8.x4.shared.b16 {%0,%1,%2,%3}, [%4];"
        : "=r"(r.x), "=r"(r.y), "=r"(r.z), "=r"(r.w) : "r"(addr));
    return r;
}

__device__ __forceinline__ void mma_tf32(float c[4], const uint4 a, const uint32_t b0, const uint32_t b1) {
    asm volatile(
        "mma.sync.aligned.m16n8k8.row.col.f32.tf32.tf32.f32 "
        "{%0,%1,%2,%3}, {%4,%5,%6,%7}, {%8,%9}, {%0,%1,%2,%3};"
        : "+f"(c[0]), "+f"(c[1]), "+f"(c[2]), "+f"(c[3])
        : "r"(a.x), "r"(a.y), "r"(a.z), "r"(a.w), "r"(b0), "r"(b1));
}

// profile-slot shifter: 1 dummy -> ncu's fixed slot (our 4th launch) = weff
__global__ void dummy_kernel() {}

// ===================================================================
// G1 split-K (R11 ordering: staging STS after the full mma block)
// CTA tile 128m x 128n x 32k, 128 threads = 4 warps, warp tile 64x64.
// grid (2=n, 32=m, 4=kz) = 256 CTAs, 2 CTAs/SM.
// ===================================================================
__global__ void __launch_bounds__(128, 2) g1_kernel(
    const float* __restrict__ x, const float* __restrict__ w_emb)
{
    extern __shared__ uint32_t dsm[];
    uint32_t* sA[2] = { dsm,               dsm + TILE_U32 };
    uint32_t* sB[2] = { dsm + 2*TILE_U32,  dsm + 3*TILE_U32 };

    const int tid  = threadIdx.x;
    const int lane = tid & 31;
    const int warp = tid >> 5;
    const int wm = (warp >> 1) * 64;
    const int wn = (warp & 1) * 64;
    const long bm = (long)blockIdx.y * 128;
    const long bn = (long)blockIdx.x * 128;
    const long kbase = (long)blockIdx.z * KCHUNK;

    const int srow8 = tid >> 3;             // 0..15
    const int sc8   = (tid & 7) * 4;        // 0,4,...,28
    const float* Abase = x + (bm + srow8) * VV + kbase + sc8;
    const float* Bbase = w_emb + (bn + srow8) * VV + kbase + sc8;
    const long rowstep = 16L * VV;

    const uint32_t sAb[2] = { smem_u32(sA[0]), smem_u32(sA[1]) };
    const uint32_t sBb[2] = { smem_u32(sB[0]), smem_u32(sB[1]) };

    const int aRow = ((lane >> 3) & 1) * 8 + (lane & 7);
    const int aCol = (lane >> 4) * 4;
    const int bRow = ((lane >> 4) & 1) * 8 + (lane & 7);
    const int bCol = ((lane >> 3) & 1) * 4;

    float acc[4][8][4] = {};
    float4 pa[8], pb[8];

    #pragma unroll
    for (int i = 0; i < 8; i++) {
        pa[i] = *reinterpret_cast<const float4*>(Abase + i * rowstep);
        pb[i] = *reinterpret_cast<const float4*>(Bbase + i * rowstep);
    }
    #pragma unroll
    for (int i = 0; i < 8; i++) {
        uint4 au = { f2tf32(pa[i].x), f2tf32(pa[i].y), f2tf32(pa[i].z), f2tf32(pa[i].w) };
        uint4 bu = { f2tf32(pb[i].x), f2tf32(pb[i].y), f2tf32(pb[i].z), f2tf32(pb[i].w) };
        *reinterpret_cast<uint4*>(&sA[0][(srow8 + 16 * i) * STR + sc8]) = au;
        *reinterpret_cast<uint4*>(&sB[0][(srow8 + 16 * i) * STR + sc8]) = bu;
    }
    __syncthreads();

    const int nkt = KCHUNK / BK32;          // 64
    for (int kt = 0; kt < nkt; kt++) {
        const int cur = kt & 1;
        const bool more = (kt + 1) < nkt;

        if (more) {
            const float* Ap = Abase + (kt + 1) * BK32;
            const float* Bp = Bbase + (kt + 1) * BK32;
            #pragma unroll
            for (int i = 0; i < 8; i++) {
                pa[i] = *reinterpret_cast<const float4*>(Ap + i * rowstep);
                pb[i] = *reinterpret_cast<const float4*>(Bp + i * rowstep);
            }
        }

        const uint32_t ab = sAb[cur];
        const uint32_t bb = sBb[cur];
        #pragma unroll
        for (int ks = 0; ks < 4; ks++) {
            const int k0 = ks * 8;
            uint4 af[4], bf[4];
            #pragma unroll
            for (int mi = 0; mi < 4; mi++)
                af[mi] = ldsm_x4(ab + ((wm + mi * 16 + aRow) * STR + k0 + aCol) * 4);
            #pragma unroll
            for (int q = 0; q < 4; q++)
                bf[q] = ldsm_x4(bb + ((wn + q * 16 + bRow) * STR + k0 + bCol) * 4);

            #pragma unroll
            for (int mi = 0; mi < 4; mi++) {
                #pragma unroll
                for (int nt = 0; nt < 8; nt++) {
                    const int q = nt >> 1;
                    if (nt & 1) mma_tf32(acc[mi][nt], af[mi], bf[q].z, bf[q].w);
                    else        mma_tf32(acc[mi][nt], af[mi], bf[q].x, bf[q].y);
                }
            }
        }

        if (more) {
            uint32_t* dA = sA[cur ^ 1];
            uint32_t* dB = sB[cur ^ 1];
            #pragma unroll
            for (int i = 0; i < 8; i++) {
                uint4 au = { f2tf32(pa[i].x), f2tf32(pa[i].y), f2tf32(pa[i].z), f2tf32(pa[i].w) };
                uint4 bu = { f2tf32(pb[i].x), f2tf32(pb[i].y), f2tf32(pb[i].z), f2tf32(pb[i].w) };
                *reinterpret_cast<uint4*>(&dA[(srow8 + 16 * i) * STR + sc8]) = au;
                *reinterpret_cast<uint4*>(&dB[(srow8 + 16 * i) * STR + sc8]) = bu;
            }
        }
        __syncthreads();
    }

    float* P = &g_p1[blockIdx.z][0][0];
    #pragma unroll
    for (int mi = 0; mi < 4; mi++) {
        #pragma unroll
        for (int nt = 0; nt < 8; nt++) {
            long row = bm + wm + mi * 16 + (lane >> 2);
            long col = bn + wn + nt * 8 + (lane & 3) * 2;
            *reinterpret_cast<float2*>(&P[row * EE + col]) =
                make_float2(acc[mi][nt][0], acc[mi][nt][1]);
            *reinterpret_cast<float2*>(&P[(row + 8) * EE + col]) =
                make_float2(acc[mi][nt][2], acc[mi][nt][3]);
        }
    }
}

// ===================================================================
// G3 tensorized: y[b] = relu(h[b] @ Weff[b]^T + b_red)
// grid (2 = n-tile, 32 = batch) x 128, dynamic smem 72 KB.
// ===================================================================
__global__ void __launch_bounds__(128, 2) g3_kernel(const float* __restrict__ b_red)
{
    extern __shared__ uint32_t dsm[];
    uint32_t* sA[2] = { dsm,               dsm + TILE_U32 };
    uint32_t* sB[2] = { dsm + 2*TILE_U32,  dsm + 3*TILE_U32 };

    const int tid  = threadIdx.x;
    const int lane = tid & 31;
    const int warp = tid >> 5;
    const int wm = (warp >> 1) * 64;
    const int wn = (warp & 1) * 64;
    const int batch = blockIdx.y;
    const long bn = (long)blockIdx.x * 128;

    const float* A = g_h + (long)batch * SS * EE;
    const float* B = g_weff + (long)batch * EE * EE;
    float* C = g_y + (long)batch * SS * EE;

    const int srow8 = tid >> 3;
    const int sc8   = (tid & 7) * 4;
    const float* Abase = A + (long)srow8 * EE + sc8;
    const float* Bbase = B + (bn + srow8) * EE + sc8;
    const long rowstep = 16L * EE;

    const uint32_t sAb[2] = { smem_u32(sA[0]), smem_u32(sA[1]) };
    const uint32_t sBb[2] = { smem_u32(sB[0]), smem_u32(sB[1]) };

    const int aRow = ((lane >> 3) & 1) * 8 + (lane & 7);
    const int aCol = (lane >> 4) * 4;
    const int bRow = ((lane >> 4) & 1) * 8 + (lane & 7);
    const int bCol = ((lane >> 3) & 1) * 4;

    float acc[4][8][4] = {};
    float4 pa[8], pb[8];

    #pragma unroll
    for (int i = 0; i < 8; i++) {
        pa[i] = *reinterpret_cast<const float4*>(Abase + i * rowstep);
        pb[i] = *reinterpret_cast<const float4*>(Bbase + i * rowstep);
    }
    #pragma unroll
    for (int i = 0; i < 8; i++) {
        uint4 au = { f2tf32(pa[i].x), f2tf32(pa[i].y), f2tf32(pa[i].z), f2tf32(pa[i].w) };
        uint4 bu = { f2tf32(pb[i].x), f2tf32(pb[i].y), f2tf32(pb[i].z), f2tf32(pb[i].w) };
        *reinterpret_cast<uint4*>(&sA[0][(srow8 + 16 * i) * STR + sc8]) = au;
        *reinterpret_cast<uint4*>(&sB[0][(srow8 + 16 * i) * STR + sc8]) = bu;
    }
    __syncthreads();

    const int nkt = EE / BK32;              // 8
    for (int kt = 0; kt < nkt; kt++) {
        const int cur = kt & 1;
        const bool more = (kt + 1) < nkt;

        if (more) {
            const float* Ap = Abase + (kt + 1) * BK32;
            const float* Bp = Bbase + (kt + 1) * BK32;
            #pragma unroll
            for (int i = 0; i < 8; i++) {
                pa[i] = *reinterpret_cast<const float4*>(Ap + i * rowstep);
                pb[i] = *reinterpret_cast<const float4*>(Bp + i * rowstep);
            }
        }

        const uint32_t ab = sAb[cur];
        const uint32_t bb = sBb[cur];
        #pragma unroll
        for (int ks = 0; ks < 4; ks++) {
            const int k0 = ks * 8;
            uint4 af[4], bf[4];
            #pragma unroll
            for (int mi = 0; mi < 4; mi++)
                af[mi] = ldsm_x4(ab + ((wm + mi * 16 + aRow) * STR + k0 + aCol) * 4);
            #pragma unroll
            for (int q = 0; q < 4; q++)
                bf[q] = ldsm_x4(bb + ((wn + q * 16 + bRow) * STR + k0 + bCol) * 4);
            #pragma unroll
            for (int mi = 0; mi < 4; mi++) {
                #pragma unroll
                for (int nt = 0; nt < 8; nt++) {
                    const int q = nt >> 1;
                    if (nt & 1) mma_tf32(acc[mi][nt], af[mi], bf[q].z, bf[q].w);
                    else        mma_tf32(acc[mi][nt], af[mi], bf[q].x, bf[q].y);
                }
            }
        }

        if (more) {
            uint32_t* dA = sA[cur ^ 1];
            uint32_t* dB = sB[cur ^ 1];
            #pragma unroll
            for (int i = 0; i < 8; i++) {
                uint4 au = { f2tf32(pa[i].x), f2tf32(pa[i].y), f2tf32(pa[i].z), f2tf32(pa[i].w) };
                uint4 bu = { f2tf32(pb[i].x), f2tf32(pb[i].y), f2tf32(pb[i].z), f2tf32(pb[i].w) };
                *reinterpret_cast<uint4*>(&dA[(srow8 + 16 * i) * STR + sc8]) = au;
                *reinterpret_cast<uint4*>(&dB[(srow8 + 16 * i) * STR + sc8]) = bu;
            }
        }
        __syncthreads();
    }

    #pragma unroll
    for (int mi = 0; mi < 4; mi++) {
        #pragma unroll
        for (int nt = 0; nt < 8; nt++) {
            long row = wm + mi * 16 + (lane >> 2);
            long col = bn + wn + nt * 8 + (lane & 3) * 2;
            float b0 = b_red[col], b1 = b_red[col + 1];
            float v0 = fmaxf(acc[mi][nt][0] + b0, 0.f);
            float v1 = fmaxf(acc[mi][nt][1] + b1, 0.f);
            float v2 = fmaxf(acc[mi][nt][2] + b0, 0.f);
            float v3 = fmaxf(acc[mi][nt][3] + b1, 0.f);
            *reinterpret_cast<float2*>(&C[row * EE + col])       = make_float2(v0, v1);
            *reinterpret_cast<float2*>(&C[(row + 8) * EE + col]) = make_float2(v2, v3);
        }
    }
}

// ---------------- h = relu(sum partials + bias); rowsum -> s ----------------
__global__ void __launch_bounds__(256) h_reduce_kernel(const float* __restrict__ b_emb)
{
    const int row = blockIdx.x;
    const int e = threadIdx.x;
    const int lane = e & 31;
    const int warp = e >> 5;

    float v = b_emb[e];
    #pragma unroll
    for (int ks = 0; ks < KSPLIT; ks++) v += g_p1[ks][row][e];
    v = fmaxf(v, 0.f);
    g_h[(long)row * EE + e] = v;

    float s = v;
    #pragma unroll
    for (int o = 16; o; o >>= 1) s += __shfl_xor_sync(0xffffffffu, s, o);
    __shared__ float red[8];
    if (lane == 0) red[warp] = s;
    __syncthreads();
    if (e == 0) {
        float t = 0.f;
        #pragma unroll
        for (int i = 0; i < 8; i++) t += red[i];
        g_s[row] = t;
    }
}

// ---------------- G2: Weff[b,e,j] = sum_k s[b,k]*w_red[e, k*E+j] ----------------
// launch_bounds (256,2): cap regs at 128 -> 2 CTAs/SM (was 164 regs, 1 CTA/SM).
__global__ void __launch_bounds__(256, 2) weff_kernel(const float* __restrict__ w_red)
{
    __shared__ float ss[BB * SS];
    int tid = threadIdx.x;
    for (int i = tid; i < BB * SS; i += 256) ss[i] = g_s[i];
    __syncthreads();

    int e = blockIdx.x;
    const float* w = w_red + (long)e * (SS * EE) + tid;
    float acc[BB];
    #pragma unroll
    for (int b = 0; b < BB; b++) acc[b] = 0.f;

    #pragma unroll 8
    for (int k = 0; k < SS; k++) {
        float wv = w[(long)k * EE];
        #pragma unroll
        for (int b = 0; b < BB; b++) acc[b] += ss[b * SS + k] * wv;
    }
    #pragma unroll
    for (int b = 0; b < BB; b++)
        g_weff[(long)b * (EE * EE) + (long)e * EE + tid] = acc[b];
}

// ---------------- G4 split-K ----------------
__global__ void __launch_bounds__(256, 2) red2_partial_kernel(const float* __restrict__ w_red2)
{
    __shared__ float ys[32][68];
    __shared__ float ws[64][65];
    int tid = threadIdx.x;
    int e_base = blockIdx.x * 64;
    long k_base = (long)blockIdx.y * 512;
    int el = tid & 63;
    int bb = (tid >> 6) * 8;
    float acc[8] = {};

    for (int k0 = 0; k0 < 512; k0 += 64) {
        #pragma unroll
        for (int i = 0; i < 2; i++) {
            int idx = tid + i * 256;
            int row = idx >> 4;
            int c4 = (idx & 15) * 4;
            float4 v = *reinterpret_cast<const float4*>(
                &g_y[(long)row * (SS * EE) + k_base + k0 + c4]);
            *reinterpret_cast<float4*>(&ys[row][c4]) = v;
        }
        #pragma unroll
        for (int i = 0; i < 4; i++) {
            int idx = tid + i * 256;
            int row = idx >> 4;
            int c4 = (idx & 15) * 4;
            float4 v = *reinterpret_cast<const float4*>(
                &w_red2[(long)(e_base + row) * (SS * EE) + k_base + k0 + c4]);
            ws[row][c4] = v.x; ws[row][c4 + 1] = v.y;
            ws[row][c4 + 2] = v.z; ws[row][c4 + 3] = v.w;
        }
        __syncthreads();
        #pragma unroll 8
        for (int kk = 0; kk < 64; kk++) {
            float wv = ws[el][kk];
            #pragma unroll
            for (int i = 0; i < 8; i++) acc[i] += ys[bb + i][kk] * wv;
        }
        __syncthreads();
    }
    #pragma unroll
    for (int i = 0; i < 8; i++)
        g_part[(long)blockIdx.y * (BB * EE) + (bb + i) * EE + e_base + el] = acc[i];
}

__global__ void red2_reduce_kernel(const float* __restrict__ b_red2)
{
    int idx = blockIdx.x * 256 + threadIdx.x;
    float s = b_red2[idx & 255];
    #pragma unroll 8
    for (int ks = 0; ks < 64; ks++) s += g_part[(long)ks * (BB * EE) + idx];
    g_y2[idx] = fmaxf(s, 0.f);
}

// ---------------- G5: out = y2 @ w_out^T + b_out ----------------
__global__ void __launch_bounds__(256, 2) out_kernel(
    const float* __restrict__ w_out, const float* __restrict__ b_out,
    float* __restrict__ out)
{
    __shared__ float ys[32][68];
    __shared__ float ws[64][65];
    int tid = threadIdx.x;
    int v_base = blockIdx.x * 64;
    int vl = tid & 63;
    int bb = (tid >> 6) * 8;
    float acc[8] = {};

    for (int k0 = 0; k0 < EE; k0 += 64) {
        #pragma unroll
        for (int i = 0; i < 2; i++) {
            int idx = tid + i * 256;
            int row = idx >> 4;
            int c4 = (idx & 15) * 4;
            float4 v = *reinterpret_cast<const float4*>(&g_y2[row * EE + k0 + c4]);
            *reinterpret_cast<float4*>(&ys[row][c4]) = v;
        }
        #pragma unroll
        for (int i = 0; i < 4; i++) {
            int idx = tid + i * 256;
            int row = idx >> 4;
            int c4 = (idx & 15) * 4;
            float4 v = *reinterpret_cast<const float4*>(
                &w_out[(long)(v_base + row) * EE + k0 + c4]);
            ws[row][c4] = v.x; ws[row][c4 + 1] = v.y;
            ws[row][c4 + 2] = v.z; ws[row][c4 + 3] = v.w;
        }
        __syncthreads();
        #pragma unroll 8
        for (int kk = 0; kk < 64; kk++) {
            float wv = ws[vl][kk];
            #pragma unroll
            for (int i = 0; i < 8; i++) acc[i] += ys[bb + i][kk] * wv;
        }
        __syncthreads();
    }
    float bo = b_out[v_base + vl];
    #pragma unroll
    for (int i = 0; i < 8; i++)
        out[(long)(bb + i) * VV + v_base + vl] = acc[i] + bo;
}

// ---------------- launch ----------------
extern "C" void kernel_launch(void* const* d_in, const int* in_sizes, int n_in,
                              void* d_out, int out_size)
{
    const float* x      = (const float*)d_in[0];
    const float* w_emb  = (const float*)d_in[1];
    const float* b_emb  = (const float*)d_in[2];
    const float* w_red  = (const float*)d_in[3];
    const float* b_red  = (const float*)d_in[4];
    const float* w_red2 = (const float*)d_in[5];
    const float* b_red2 = (const float*)d_in[6];
    const float* w_out  = (const float*)d_in[7];
    const float* b_out  = (const float*)d_in[8];
    float* out = (float*)d_out;

    cudaFuncSetAttribute(g1_kernel, cudaFuncAttributeMaxDynamicSharedMemorySize, G1_DSMEM);
    cudaFuncSetAttribute(g3_kernel, cudaFuncAttributeMaxDynamicSharedMemorySize, G1_DSMEM);

    dummy_kernel<<<1, 32>>>();                                   // 1 dummy: ncu slot -> weff
    g1_kernel<<<dim3(2, 32, KSPLIT), 128, G1_DSMEM>>>(x, w_emb); // G1 partials
    h_reduce_kernel<<<MR, 256>>>(b_emb);                         // h + rowsum
    weff_kernel<<<256, 256>>>(w_red);                            // Weff  (profiled)
    g3_kernel<<<dim3(2, 32), 128, G1_DSMEM>>>(b_red);            // y (tensorized)
    red2_partial_kernel<<<dim3(4, 64), 256>>>(w_red2);           // G4 partials
    red2_reduce_kernel<<<32, 256>>>(b_red2);                     // y2
    out_kernel<<<128, 256>>>(w_out, b_out, out);                 // out
}